// round 15
// baseline (speedup 1.0000x reference)
#include <cuda_runtime.h>
#include <cuda_fp16.h>
#include <math.h>
#include <stdint.h>

// Problem constants (fixed per reference)
#define BSZ    4
#define TLEN   2048
#define DMODEL 1024
#define HEADS  16
#define HDIM   64
#define RAD    4
#define MROWS  (BSZ * TLEN)   // 8192

// ---------------------------------------------------------------------------
// Scratch (__device__ globals; no cudaMalloc allowed)
// ---------------------------------------------------------------------------
__device__ __align__(16) __half g_qkv_h[(size_t)MROWS * 3 * DMODEL];  // 48 MB
__device__ __align__(16) __half g_x_h[(size_t)MROWS * DMODEL];
__device__ __align__(16) __half g_wq_h[(size_t)3 * DMODEL * DMODEL];
__device__ __align__(16) __half g_wp_h[(size_t)DMODEL * DMODEL];
__device__ __align__(16) __half g_att_h[(size_t)MROWS * DMODEL];

// ---------------------------------------------------------------------------
// PTX helpers
// ---------------------------------------------------------------------------
__device__ __forceinline__ void cp16(uint32_t dst, const void* src) {
    asm volatile("cp.async.cg.shared.global [%0], [%1], 16;" :: "r"(dst), "l"(src));
}
__device__ __forceinline__ void cp_commit() {
    asm volatile("cp.async.commit_group;" ::: "memory");
}
template <int N>
__device__ __forceinline__ void cp_wait() {
    asm volatile("cp.async.wait_group %0;" :: "n"(N) : "memory");
}
__device__ __forceinline__ void ldsm4(uint32_t* r, uint32_t addr) {
    asm volatile("ldmatrix.sync.aligned.m8n8.x4.shared.b16 {%0,%1,%2,%3}, [%4];"
                 : "=r"(r[0]), "=r"(r[1]), "=r"(r[2]), "=r"(r[3]) : "r"(addr));
}
__device__ __forceinline__ void mma16816(float* d, const uint32_t* a,
                                         uint32_t b0, uint32_t b1) {
    asm volatile(
        "mma.sync.aligned.m16n8k16.row.col.f32.f16.f16.f32 "
        "{%0,%1,%2,%3},{%4,%5,%6,%7},{%8,%9},{%0,%1,%2,%3};"
        : "+f"(d[0]), "+f"(d[1]), "+f"(d[2]), "+f"(d[3])
        : "r"(a[0]), "r"(a[1]), "r"(a[2]), "r"(a[3]), "r"(b0), "r"(b1));
}

// SW128 swizzle over 128B rows: 16B chunk c (0..7) XOR row&7 -> conflict-free
// LDSM and cp.async stores.
#define SWZ8(row, c) (((c) ^ ((row) & 7)))

// ---------------------------------------------------------------------------
// Cast fp32 -> fp16, 4 elems/thread
// ---------------------------------------------------------------------------
__global__ void cast_h(const float4* __restrict__ in,
                       __half2* __restrict__ hi, int n4)
{
    int i = blockIdx.x * blockDim.x + threadIdx.x;
    if (i >= n4) return;
    float4 v = in[i];
    __half2 h0; h0.x = __float2half(v.x); h0.y = __float2half(v.y);
    __half2 h1; h1.x = __float2half(v.z); h1.y = __float2half(v.w);
    hi[2 * i] = h0;  hi[2 * i + 1] = h1;
}

// ---------------------------------------------------------------------------
// Tensor-core GEMM (TN): C[M,N] = A[M,K] @ B[N,K]^T + bias, fp16 in, fp32 acc.
// CTA tile 128x128x64, 8 warps (2x4) of 64x32; 2 smem planes per stage,
// 3 stages, prefetch distance 2, 2 CTAs/SM. (Proven config — round 14.)
// ---------------------------------------------------------------------------
#define STAGE_BYTES 32768
#define NSTAGE 3
#define GEMM_SMEM (NSTAGE * STAGE_BYTES)

template <bool HALF_OUT>
__global__ __launch_bounds__(256, 2)
void gemm_fp16(const __half* __restrict__ A,
               const __half* __restrict__ B,
               const float* __restrict__ bias,
               void* __restrict__ Cv,
               int M, int N, int K)
{
    extern __shared__ char smem[];
    const uint32_t sbase = (uint32_t)__cvta_generic_to_shared(smem);

    const int tid  = threadIdx.x;
    const int lane = tid & 31;
    const int warp = tid >> 5;
    const int bm = blockIdx.y * 128;
    const int bn = blockIdx.x * 128;
    const int wm = (warp >> 2) * 64;
    const int wn = (warp & 3) * 32;

    const int lrow = tid >> 1;
    const int c0   = (tid & 1) * 4;
    const __half* srcA = A + (size_t)(bm + lrow) * K;
    const __half* srcB = B + (size_t)(bn + lrow) * K;
    uint32_t sd[4];
#pragma unroll
    for (int j = 0; j < 4; j++)
        sd[j] = (uint32_t)(lrow * 128 + SWZ8(lrow, c0 + j) * 16);

    auto load_stage = [&](int s, int k0) {
        const uint32_t base = sbase + s * STAGE_BYTES;
#pragma unroll
        for (int j = 0; j < 4; j++)
            cp16(base + sd[j], srcA + k0 + (c0 + j) * 8);
#pragma unroll
        for (int j = 0; j < 4; j++)
            cp16(base + 16384 + sd[j], srcB + k0 + (c0 + j) * 8);
        cp_commit();
    };

    float acc[4][4][4];
#pragma unroll
    for (int i = 0; i < 4; i++)
#pragma unroll
        for (int j = 0; j < 4; j++)
#pragma unroll
            for (int k = 0; k < 4; k++) acc[i][j][k] = 0.f;

    const int NIT = K >> 6;            // 16
    load_stage(0, 0);
    load_stage(1, 64);

    const int r16 = lane & 15;
    const int khalf = lane >> 4;
    const int wrot = warp & 3;

#pragma unroll 1
    for (int it = 0; it < NIT; it++) {
        if (it + 1 < NIT) cp_wait<1>(); else cp_wait<0>();
        __syncthreads();

        if (it + 2 < NIT) {
            int s2 = it + 2;
            s2 -= (s2 / 3) * 3;
            load_stage(s2, (it + 2) * 64);
        }

        const int s = it - (it / 3) * 3;
        const uint32_t stbase = sbase + s * STAGE_BYTES;

#pragma unroll
        for (int kx = 0; kx < 4; kx++) {
            const int kk = (kx + wrot) & 3;
            const int kc = kk * 2 + khalf;

            uint32_t bfr[2][4];
#pragma unroll
            for (int ng = 0; ng < 2; ng++) {
                const int row = wn + ng * 16 + r16;
                const uint32_t off = row * 128 + SWZ8(row, kc) * 16;
                ldsm4(bfr[ng], stbase + 16384 + off);
            }
#pragma unroll
            for (int mb = 0; mb < 4; mb++) {
                uint32_t afr[4];
                const int row = wm + mb * 16 + r16;
                const uint32_t off = row * 128 + SWZ8(row, kc) * 16;
                ldsm4(afr, stbase + off);
#pragma unroll
                for (int nb = 0; nb < 4; nb++) {
                    const int ng = nb >> 1, j = nb & 1;
                    mma16816(acc[mb][nb], afr, bfr[ng][j], bfr[ng][2 + j]);
                }
            }
        }
    }

    // ---- Epilogue: bias add; fp16 or fp32 stores ----
    const int g  = lane >> 2;
    const int t2 = (lane & 3) * 2;
#pragma unroll
    for (int nb = 0; nb < 4; nb++) {
        const int col = bn + wn + nb * 8 + t2;
        const float bx = __ldg(bias + col), by = __ldg(bias + col + 1);
#pragma unroll
        for (int mb = 0; mb < 4; mb++) {
            const int row = bm + wm + mb * 16 + g;
            if (HALF_OUT) {
                __half* C = (__half*)Cv;
                __half2 v0, v1;
                v0.x = __float2half(acc[mb][nb][0] + bx);
                v0.y = __float2half(acc[mb][nb][1] + by);
                v1.x = __float2half(acc[mb][nb][2] + bx);
                v1.y = __float2half(acc[mb][nb][3] + by);
                *(__half2*)(C + (size_t)row * N + col)       = v0;
                *(__half2*)(C + (size_t)(row + 8) * N + col) = v1;
            } else {
                float* C = (float*)Cv;
                float2 v0 = make_float2(acc[mb][nb][0] + bx, acc[mb][nb][1] + by);
                float2 v1 = make_float2(acc[mb][nb][2] + bx, acc[mb][nb][3] + by);
                *(float2*)(C + (size_t)row * N + col)       = v0;
                *(float2*)(C + (size_t)(row + 8) * N + col) = v1;
            }
        }
    }
}

// ---------------------------------------------------------------------------
// Banded attention v2: ONE THREAD per (b,t,h). No shuffles.
// Pass 1: stream q in 16B chunks against 9 banded k rows -> s[9] in registers.
// Softmax in-thread. Pass 2: stream v chunks into 8 fp32 accumulators, store
// 16B fp16 per chunk. h is the fastest thread index -> half-warp lanes read
// 16 adjacent 128B h-slices of the SAME k/v row; each row reused by 9
// neighboring t threads -> L1-resident.
// ---------------------------------------------------------------------------
__device__ __forceinline__ float dot8(uint4 a, uint4 b) {
    const __half2* ah = (const __half2*)&a;
    const __half2* bh = (const __half2*)&b;
    float r = 0.f;
#pragma unroll
    for (int i = 0; i < 4; i++) {
        float2 af = __half22float2(ah[i]);
        float2 bf = __half22float2(bh[i]);
        r = fmaf(af.x, bf.x, r);
        r = fmaf(af.y, bf.y, r);
    }
    return r;
}

__global__ __launch_bounds__(256)
void focal_attn_t(const __half* __restrict__ qkv,
                  __half* __restrict__ out_h)
{
    const int gid = blockIdx.x * 256 + threadIdx.x;   // 0 .. B*T*H-1
    const int h  = gid & (HEADS - 1);
    const int bt = gid >> 4;
    const int t  = bt & (TLEN - 1);
    const int b  = bt >> 11;

    const size_t row_stride = 3 * DMODEL;
    const __half* qrow = qkv + (size_t)bt * row_stride + h * HDIM;
    const __half* kbase = qkv + (size_t)(b * TLEN) * row_stride + DMODEL + h * HDIM;
    const __half* vbase = kbase + DMODEL;

    bool ok[9];
#pragma unroll
    for (int jj = 0; jj < 9; jj++)
        ok[jj] = ((unsigned)(t - RAD + jj) < (unsigned)TLEN);

    // ---- Pass 1: scores ----
    float s[9];
#pragma unroll
    for (int jj = 0; jj < 9; jj++) s[jj] = 0.f;

#pragma unroll
    for (int c = 0; c < 8; c++) {
        const uint4 qv = *(const uint4*)(qrow + c * 8);
#pragma unroll
        for (int jj = 0; jj < 9; jj++) {
            if (ok[jj]) {
                const int j = t - RAD + jj;
                const uint4 kv = *(const uint4*)(kbase + (size_t)j * row_stride + c * 8);
                s[jj] += dot8(qv, kv);
            }
        }
    }

    // ---- Softmax over the 9 slots ----
    float m = -INFINITY;
#pragma unroll
    for (int jj = 0; jj < 9; jj++)
        if (ok[jj]) m = fmaxf(m, s[jj] * 0.125f);

    float p[9], psum = 0.f;
#pragma unroll
    for (int jj = 0; jj < 9; jj++) {
        p[jj] = ok[jj] ? expf(s[jj] * 0.125f - m) : 0.f;
        psum += p[jj];
    }
    const float inv = 1.f / psum;
#pragma unroll
    for (int jj = 0; jj < 9; jj++) p[jj] *= inv;

    // ---- Pass 2: weighted V, streamed per 16B chunk ----
    __half* orow = out_h + (size_t)bt * DMODEL + h * HDIM;
#pragma unroll
    for (int c = 0; c < 8; c++) {
        float acc[8];
#pragma unroll
        for (int i = 0; i < 8; i++) acc[i] = 0.f;
#pragma unroll
        for (int jj = 0; jj < 9; jj++) {
            if (ok[jj]) {
                const int j = t - RAD + jj;
                const uint4 vv = *(const uint4*)(vbase + (size_t)j * row_stride + c * 8);
                const __half2* vh = (const __half2*)&vv;
#pragma unroll
                for (int i = 0; i < 4; i++) {
                    float2 vf = __half22float2(vh[i]);
                    acc[2 * i]     = fmaf(p[jj], vf.x, acc[2 * i]);
                    acc[2 * i + 1] = fmaf(p[jj], vf.y, acc[2 * i + 1]);
                }
            }
        }
        uint4 ov;
        __half2* oh = (__half2*)&ov;
#pragma unroll
        for (int i = 0; i < 4; i++) {
            __half2 hv;
            hv.x = __float2half(acc[2 * i]);
            hv.y = __float2half(acc[2 * i + 1]);
            oh[i] = hv;
        }
        *(uint4*)(orow + c * 8) = ov;
    }
}

// ---------------------------------------------------------------------------
// Launch: cast inputs -> QKV GEMM (fp16 out) -> attention -> proj GEMM
// ---------------------------------------------------------------------------
extern "C" void kernel_launch(void* const* d_in, const int* in_sizes, int n_in,
                              void* d_out, int out_size)
{
    const float* x      = (const float*)d_in[0];
    const float* w_qkv  = (const float*)d_in[1];
    const float* b_qkv  = (const float*)d_in[2];
    const float* w_proj = (const float*)d_in[3];
    const float* b_proj = (const float*)d_in[4];
    float* out = (float*)d_out;

    __half *qkvh, *xh, *wqh, *wph, *ath;
    cudaGetSymbolAddress((void**)&qkvh, g_qkv_h);
    cudaGetSymbolAddress((void**)&xh,  g_x_h);
    cudaGetSymbolAddress((void**)&wqh, g_wq_h);
    cudaGetSymbolAddress((void**)&wph, g_wp_h);
    cudaGetSymbolAddress((void**)&ath, g_att_h);

    cudaFuncSetAttribute(gemm_fp16<true>,
                         cudaFuncAttributeMaxDynamicSharedMemorySize, GEMM_SMEM);
    cudaFuncSetAttribute(gemm_fp16<false>,
                         cudaFuncAttributeMaxDynamicSharedMemorySize, GEMM_SMEM);

    // Cast inputs to fp16
    {
        int n4 = MROWS * DMODEL / 4;
        cast_h<<<(n4 + 255) / 256, 256>>>((const float4*)x, (__half2*)xh, n4);
        n4 = 3 * DMODEL * DMODEL / 4;
        cast_h<<<(n4 + 255) / 256, 256>>>((const float4*)w_qkv, (__half2*)wqh, n4);
        n4 = DMODEL * DMODEL / 4;
        cast_h<<<(n4 + 255) / 256, 256>>>((const float4*)w_proj, (__half2*)wph, n4);
    }

    // GEMM1: qkv[8192,3072] = x @ w_qkv^T + b_qkv  (fp16 out)
    {
        dim3 grid(3 * DMODEL / 128, MROWS / 128);   // 24 x 64
        gemm_fp16<true><<<grid, 256, GEMM_SMEM>>>(xh, wqh, b_qkv, qkvh,
                                                  MROWS, 3 * DMODEL, DMODEL);
    }

    // Attention: one thread per (b,t,h)
    {
        const int total = BSZ * TLEN * HEADS;       // 131072
        focal_attn_t<<<total / 256, 256>>>(qkvh, ath);
    }

    // GEMM2: out[8192,1024] = att @ w_proj^T + b_proj  (fp32 out)
    {
        dim3 grid(DMODEL / 128, MROWS / 128);       // 8 x 64
        gemm_fp16<false><<<grid, 256, GEMM_SMEM>>>(ath, wph, b_proj, out,
                                                   MROWS, DMODEL, DMODEL);
    }
}

// round 16
// speedup vs baseline: 1.2374x; 1.2374x over previous
#include <cuda_runtime.h>
#include <cuda_fp16.h>
#include <math.h>
#include <stdint.h>

// Problem constants (fixed per reference)
#define BSZ    4
#define TLEN   2048
#define DMODEL 1024
#define HEADS  16
#define HDIM   64
#define RAD    4
#define MROWS  (BSZ * TLEN)   // 8192

// ---------------------------------------------------------------------------
// Scratch (__device__ globals; no cudaMalloc allowed)
// ---------------------------------------------------------------------------
__device__ __align__(16) __half g_qkv_h[(size_t)MROWS * 3 * DMODEL];  // 48 MB
__device__ __align__(16) __half g_x_h[(size_t)MROWS * DMODEL];
__device__ __align__(16) __half g_wq_h[(size_t)3 * DMODEL * DMODEL];
__device__ __align__(16) __half g_wp_h[(size_t)DMODEL * DMODEL];
__device__ __align__(16) __half g_att_h[(size_t)MROWS * DMODEL];

// ---------------------------------------------------------------------------
// PTX helpers
// ---------------------------------------------------------------------------
__device__ __forceinline__ void cp16(uint32_t dst, const void* src) {
    asm volatile("cp.async.cg.shared.global [%0], [%1], 16;" :: "r"(dst), "l"(src));
}
__device__ __forceinline__ void cp_commit() {
    asm volatile("cp.async.commit_group;" ::: "memory");
}
template <int N>
__device__ __forceinline__ void cp_wait() {
    asm volatile("cp.async.wait_group %0;" :: "n"(N) : "memory");
}
__device__ __forceinline__ void ldsm4(uint32_t* r, uint32_t addr) {
    asm volatile("ldmatrix.sync.aligned.m8n8.x4.shared.b16 {%0,%1,%2,%3}, [%4];"
                 : "=r"(r[0]), "=r"(r[1]), "=r"(r[2]), "=r"(r[3]) : "r"(addr));
}
__device__ __forceinline__ void mma16816(float* d, const uint32_t* a,
                                         uint32_t b0, uint32_t b1) {
    asm volatile(
        "mma.sync.aligned.m16n8k16.row.col.f32.f16.f16.f32 "
        "{%0,%1,%2,%3},{%4,%5,%6,%7},{%8,%9},{%0,%1,%2,%3};"
        : "+f"(d[0]), "+f"(d[1]), "+f"(d[2]), "+f"(d[3])
        : "r"(a[0]), "r"(a[1]), "r"(a[2]), "r"(a[3]), "r"(b0), "r"(b1));
}

// SW128 swizzle over 128B rows: 16B chunk c (0..7) XOR row&7.
#define SWZ8(row, c) (((c) ^ ((row) & 7)))

// ---------------------------------------------------------------------------
// Cast fp32 -> fp16, 4 elems/thread
// ---------------------------------------------------------------------------
__global__ void cast_h(const float4* __restrict__ in,
                       __half2* __restrict__ hi, int n4)
{
    int i = blockIdx.x * blockDim.x + threadIdx.x;
    if (i >= n4) return;
    float4 v = in[i];
    __half2 h0; h0.x = __float2half(v.x); h0.y = __float2half(v.y);
    __half2 h1; h1.x = __float2half(v.z); h1.y = __float2half(v.w);
    hi[2 * i] = h0;  hi[2 * i + 1] = h1;
}

// ---------------------------------------------------------------------------
// Tensor-core GEMM (TN): fp16 in, fp32 acc. 128x128x64 tile, 8 warps,
// 3-stage cp.async pipeline, 2 CTAs/SM. (Proven config — round 14.)
// ---------------------------------------------------------------------------
#define STAGE_BYTES 32768
#define NSTAGE 3
#define GEMM_SMEM (NSTAGE * STAGE_BYTES)

template <bool HALF_OUT>
__global__ __launch_bounds__(256, 2)
void gemm_fp16(const __half* __restrict__ A,
               const __half* __restrict__ B,
               const float* __restrict__ bias,
               void* __restrict__ Cv,
               int M, int N, int K)
{
    extern __shared__ char smem[];
    const uint32_t sbase = (uint32_t)__cvta_generic_to_shared(smem);

    const int tid  = threadIdx.x;
    const int lane = tid & 31;
    const int warp = tid >> 5;
    const int bm = blockIdx.y * 128;
    const int bn = blockIdx.x * 128;
    const int wm = (warp >> 2) * 64;
    const int wn = (warp & 3) * 32;

    const int lrow = tid >> 1;
    const int c0   = (tid & 1) * 4;
    const __half* srcA = A + (size_t)(bm + lrow) * K;
    const __half* srcB = B + (size_t)(bn + lrow) * K;
    uint32_t sd[4];
#pragma unroll
    for (int j = 0; j < 4; j++)
        sd[j] = (uint32_t)(lrow * 128 + SWZ8(lrow, c0 + j) * 16);

    auto load_stage = [&](int s, int k0) {
        const uint32_t base = sbase + s * STAGE_BYTES;
#pragma unroll
        for (int j = 0; j < 4; j++)
            cp16(base + sd[j], srcA + k0 + (c0 + j) * 8);
#pragma unroll
        for (int j = 0; j < 4; j++)
            cp16(base + 16384 + sd[j], srcB + k0 + (c0 + j) * 8);
        cp_commit();
    };

    float acc[4][4][4];
#pragma unroll
    for (int i = 0; i < 4; i++)
#pragma unroll
        for (int j = 0; j < 4; j++)
#pragma unroll
            for (int k = 0; k < 4; k++) acc[i][j][k] = 0.f;

    const int NIT = K >> 6;            // 16
    load_stage(0, 0);
    load_stage(1, 64);

    const int r16 = lane & 15;
    const int khalf = lane >> 4;
    const int wrot = warp & 3;

#pragma unroll 1
    for (int it = 0; it < NIT; it++) {
        if (it + 1 < NIT) cp_wait<1>(); else cp_wait<0>();
        __syncthreads();

        if (it + 2 < NIT) {
            int s2 = it + 2;
            s2 -= (s2 / 3) * 3;
            load_stage(s2, (it + 2) * 64);
        }

        const int s = it - (it / 3) * 3;
        const uint32_t stbase = sbase + s * STAGE_BYTES;

#pragma unroll
        for (int kx = 0; kx < 4; kx++) {
            const int kk = (kx + wrot) & 3;
            const int kc = kk * 2 + khalf;

            uint32_t bfr[2][4];
#pragma unroll
            for (int ng = 0; ng < 2; ng++) {
                const int row = wn + ng * 16 + r16;
                const uint32_t off = row * 128 + SWZ8(row, kc) * 16;
                ldsm4(bfr[ng], stbase + 16384 + off);
            }
#pragma unroll
            for (int mb = 0; mb < 4; mb++) {
                uint32_t afr[4];
                const int row = wm + mb * 16 + r16;
                const uint32_t off = row * 128 + SWZ8(row, kc) * 16;
                ldsm4(afr, stbase + off);
#pragma unroll
                for (int nb = 0; nb < 4; nb++) {
                    const int ng = nb >> 1, j = nb & 1;
                    mma16816(acc[mb][nb], afr, bfr[ng][j], bfr[ng][2 + j]);
                }
            }
        }
    }

    const int g  = lane >> 2;
    const int t2 = (lane & 3) * 2;
#pragma unroll
    for (int nb = 0; nb < 4; nb++) {
        const int col = bn + wn + nb * 8 + t2;
        const float bx = __ldg(bias + col), by = __ldg(bias + col + 1);
#pragma unroll
        for (int mb = 0; mb < 4; mb++) {
            const int row = bm + wm + mb * 16 + g;
            if (HALF_OUT) {
                __half* C = (__half*)Cv;
                __half2 v0, v1;
                v0.x = __float2half(acc[mb][nb][0] + bx);
                v0.y = __float2half(acc[mb][nb][1] + by);
                v1.x = __float2half(acc[mb][nb][2] + bx);
                v1.y = __float2half(acc[mb][nb][3] + by);
                *(__half2*)(C + (size_t)row * N + col)       = v0;
                *(__half2*)(C + (size_t)(row + 8) * N + col) = v1;
            } else {
                float* C = (float*)Cv;
                float2 v0 = make_float2(acc[mb][nb][0] + bx, acc[mb][nb][1] + by);
                float2 v1 = make_float2(acc[mb][nb][2] + bx, acc[mb][nb][3] + by);
                *(float2*)(C + (size_t)row * N + col)       = v0;
                *(float2*)(C + (size_t)(row + 8) * N + col) = v1;
            }
        }
    }
}

// ---------------------------------------------------------------------------
// Banded attention v3: smem-tiled. Block = (b, 16 consecutive t) x 16 heads.
// Stage k/v halo tiles (24 rows x 1024 fp16 = 48KB each) into smem with
// coalesced 16B loads; swizzled layout (chunk c ^ (h&7)) makes both the
// fill stores and the compute reads bank-conflict-free.
// Thread (t_local, h): 9x64-dim dots from smem, in-thread softmax, weighted V.
// ---------------------------------------------------------------------------
#define ATT_ROWS   24                          // 16 + 2*RAD halo
#define ATT_ROW_B  2048                        // 1024 fp16 per row
#define ATT_TILE_B (ATT_ROWS * ATT_ROW_B)      // 48KB
#define ATT_SMEM   (2 * ATT_TILE_B)            // 96KB (K then V)

__device__ __forceinline__ float dot8s(uint4 a, uint4 b) {
    const __half2* ah = (const __half2*)&a;
    const __half2* bh = (const __half2*)&b;
    float r = 0.f;
#pragma unroll
    for (int i = 0; i < 4; i++) {
        float2 af = __half22float2(ah[i]);
        float2 bf = __half22float2(bh[i]);
        r = fmaf(af.x, bf.x, r);
        r = fmaf(af.y, bf.y, r);
    }
    return r;
}

__global__ __launch_bounds__(256, 2)
void focal_attn_s(const __half* __restrict__ qkv,
                  __half* __restrict__ out_h)
{
    extern __shared__ char smem[];
    __half* ks = (__half*)smem;
    __half* vs = (__half*)(smem + ATT_TILE_B);

    const int tid = threadIdx.x;
    const int b   = blockIdx.x >> 7;           // 4 batches
    const int t0  = (blockIdx.x & 127) * 16;   // 128 t-tiles per batch

    const size_t row_stride = 3 * DMODEL;
    const __half* kg = qkv + (size_t)(b * TLEN) * row_stride + DMODEL;
    const __half* vg = kg + DMODEL;

    // ---- Fill K and V tiles (rows t0-4 .. t0+19), coalesced + swizzled ----
    // 24 rows x 128 chunks(16B) = 3072 chunks per tensor; 12 per thread each.
#pragma unroll
    for (int i = 0; i < 12; i++) {
        const int idx  = tid + i * 256;
        const int lrow = idx >> 7;             // 0..23
        const int ch   = idx & 127;            // 0..127
        const int hh   = ch >> 3;              // head slice 0..15
        const int cc   = ch & 7;
        const int j    = t0 - RAD + lrow;
        const uint32_t dst = lrow * ATT_ROW_B + hh * 128 + ((cc ^ (hh & 7)) * 16);
        uint4 kvv = make_uint4(0, 0, 0, 0), vvv = make_uint4(0, 0, 0, 0);
        if ((unsigned)j < (unsigned)TLEN) {
            kvv = *(const uint4*)(kg + (size_t)j * row_stride + ch * 8);
            vvv = *(const uint4*)(vg + (size_t)j * row_stride + ch * 8);
        }
        *(uint4*)((char*)ks + dst) = kvv;
        *(uint4*)((char*)vs + dst) = vvv;
    }
    __syncthreads();

    // ---- Compute: thread = (t_local, h) ----
    const int tl = tid >> 4;                   // 0..15
    const int h  = tid & 15;
    const int t  = t0 + tl;
    const int bt = b * TLEN + t;

    // q row (coalesced across h)
    uint4 qv[4];
    const __half* qrow = qkv + (size_t)bt * row_stride + h * HDIM;
#pragma unroll
    for (int c = 0; c < 4; c++) qv[c] = *(const uint4*)(qrow + c * 8);
    // q chunks 0..3 of this head's 64 halves = global chunks; in smem terms a
    // head slice is 128B = 8 chunks of 16B... HDIM=64 fp16 = 128B = 8 chunks?
    // 64 halves = 128B -> 8 chunks of 16B. Wait: load all 8.
    uint4 qv2[4];
#pragma unroll
    for (int c = 0; c < 4; c++) qv2[c] = *(const uint4*)(qrow + 32 + c * 8);

    bool ok[9];
#pragma unroll
    for (int jj = 0; jj < 9; jj++)
        ok[jj] = ((unsigned)(t - RAD + jj) < (unsigned)TLEN);

    // ---- Pass 1: scores from smem K ----
    float s[9];
#pragma unroll
    for (int jj = 0; jj < 9; jj++) {
        const int lrow = tl + jj;              // 0..23
        const char* kr = (char*)ks + lrow * ATT_ROW_B + h * 128;
        float acc = 0.f;
#pragma unroll
        for (int c = 0; c < 4; c++)
            acc += dot8s(qv[c], *(const uint4*)(kr + ((c ^ (h & 7)) * 16)));
#pragma unroll
        for (int c = 4; c < 8; c++)
            acc += dot8s(qv2[c - 4], *(const uint4*)(kr + ((c ^ (h & 7)) * 16)));
        s[jj] = acc * 0.125f;                  // hd^-0.5
    }

    // ---- Softmax over the 9 slots ----
    float m = -INFINITY;
#pragma unroll
    for (int jj = 0; jj < 9; jj++)
        if (ok[jj]) m = fmaxf(m, s[jj]);

    float p[9], psum = 0.f;
#pragma unroll
    for (int jj = 0; jj < 9; jj++) {
        p[jj] = ok[jj] ? expf(s[jj] - m) : 0.f;
        psum += p[jj];
    }
    const float inv = 1.f / psum;
#pragma unroll
    for (int jj = 0; jj < 9; jj++) p[jj] *= inv;

    // ---- Pass 2: weighted V from smem ----
    float acc[16];
#pragma unroll
    for (int i = 0; i < 16; i++) acc[i] = 0.f;
    // First 32 halves (chunks 0..3)
#pragma unroll
    for (int jj = 0; jj < 9; jj++) {
        const char* vr = (char*)vs + (tl + jj) * ATT_ROW_B + h * 128;
        const float pw = p[jj];
#pragma unroll
        for (int c = 0; c < 4; c++) {
            const uint4 vv = *(const uint4*)(vr + ((c ^ (h & 7)) * 16));
            const __half2* vh = (const __half2*)&vv;
#pragma unroll
            for (int i = 0; i < 4; i++) {
                float2 vf = __half22float2(vh[i]);
                acc[c * 4 + i] = fmaf(pw, vf.x, acc[c * 4 + i]);
                // pack pairs: track x in acc, y folded below
            }
        }
    }
    // NOTE: above folds only .x lanes; redo properly with 2 accum arrays.
    // (Replaced by correct full version below.)
    // ---- correct pass 2 ----
    float ax[32];
#pragma unroll
    for (int i = 0; i < 32; i++) ax[i] = 0.f;
    float ay[32];
#pragma unroll
    for (int i = 0; i < 32; i++) ay[i] = 0.f;
#pragma unroll
    for (int jj = 0; jj < 9; jj++) {
        const char* vr = (char*)vs + (tl + jj) * ATT_ROW_B + h * 128;
        const float pw = p[jj];
#pragma unroll
        for (int c = 0; c < 8; c++) {
            const uint4 vv = *(const uint4*)(vr + ((c ^ (h & 7)) * 16));
            const __half2* vh = (const __half2*)&vv;
#pragma unroll
            for (int i = 0; i < 4; i++) {
                float2 vf = __half22float2(vh[i]);
                ax[c * 4 + i] = fmaf(pw, vf.x, ax[c * 4 + i]);
                ay[c * 4 + i] = fmaf(pw, vf.y, ay[c * 4 + i]);
            }
        }
    }

    __half* orow = out_h + (size_t)bt * DMODEL + h * HDIM;
#pragma unroll
    for (int c = 0; c < 8; c++) {
        uint4 ov;
        __half2* oh = (__half2*)&ov;
#pragma unroll
        for (int i = 0; i < 4; i++) {
            __half2 hv;
            hv.x = __float2half(ax[c * 4 + i]);
            hv.y = __float2half(ay[c * 4 + i]);
            oh[i] = hv;
        }
        *(uint4*)(orow + c * 8) = ov;
    }
}

// ---------------------------------------------------------------------------
// Launch: cast inputs -> QKV GEMM (fp16 out) -> attention -> proj GEMM
// ---------------------------------------------------------------------------
extern "C" void kernel_launch(void* const* d_in, const int* in_sizes, int n_in,
                              void* d_out, int out_size)
{
    const float* x      = (const float*)d_in[0];
    const float* w_qkv  = (const float*)d_in[1];
    const float* b_qkv  = (const float*)d_in[2];
    const float* w_proj = (const float*)d_in[3];
    const float* b_proj = (const float*)d_in[4];
    float* out = (float*)d_out;

    __half *qkvh, *xh, *wqh, *wph, *ath;
    cudaGetSymbolAddress((void**)&qkvh, g_qkv_h);
    cudaGetSymbolAddress((void**)&xh,  g_x_h);
    cudaGetSymbolAddress((void**)&wqh, g_wq_h);
    cudaGetSymbolAddress((void**)&wph, g_wp_h);
    cudaGetSymbolAddress((void**)&ath, g_att_h);

    cudaFuncSetAttribute(gemm_fp16<true>,
                         cudaFuncAttributeMaxDynamicSharedMemorySize, GEMM_SMEM);
    cudaFuncSetAttribute(gemm_fp16<false>,
                         cudaFuncAttributeMaxDynamicSharedMemorySize, GEMM_SMEM);
    cudaFuncSetAttribute(focal_attn_s,
                         cudaFuncAttributeMaxDynamicSharedMemorySize, ATT_SMEM);

    // Cast inputs to fp16
    {
        int n4 = MROWS * DMODEL / 4;
        cast_h<<<(n4 + 255) / 256, 256>>>((const float4*)x, (__half2*)xh, n4);
        n4 = 3 * DMODEL * DMODEL / 4;
        cast_h<<<(n4 + 255) / 256, 256>>>((const float4*)w_qkv, (__half2*)wqh, n4);
        n4 = DMODEL * DMODEL / 4;
        cast_h<<<(n4 + 255) / 256, 256>>>((const float4*)w_proj, (__half2*)wph, n4);
    }

    // GEMM1: qkv[8192,3072] = x @ w_qkv^T + b_qkv  (fp16 out)
    {
        dim3 grid(3 * DMODEL / 128, MROWS / 128);   // 24 x 64
        gemm_fp16<true><<<grid, 256, GEMM_SMEM>>>(xh, wqh, b_qkv, qkvh,
                                                  MROWS, 3 * DMODEL, DMODEL);
    }

    // Attention: 512 blocks (b x 128 t-tiles), smem-tiled
    {
        focal_attn_s<<<BSZ * (TLEN / 16), 256, ATT_SMEM>>>(qkvh, ath);
    }

    // GEMM2: out[8192,1024] = att @ w_proj^T + b_proj  (fp32 out)
    {
        dim3 grid(DMODEL / 128, MROWS / 128);       // 8 x 64
        gemm_fp16<false><<<grid, 256, GEMM_SMEM>>>(ath, wph, b_proj, out,
                                                   MROWS, DMODEL, DMODEL);
    }
}

// round 17
// speedup vs baseline: 1.4129x; 1.1419x over previous
#include <cuda_runtime.h>
#include <cuda_fp16.h>
#include <math.h>
#include <stdint.h>

// Problem constants (fixed per reference)
#define BSZ    4
#define TLEN   2048
#define DMODEL 1024
#define HEADS  16
#define HDIM   64
#define RAD    4
#define MROWS  (BSZ * TLEN)   // 8192

// ---------------------------------------------------------------------------
// Scratch (__device__ globals; no cudaMalloc allowed)
// ---------------------------------------------------------------------------
__device__ __align__(16) __half g_qkv_h[(size_t)MROWS * 3 * DMODEL];  // 48 MB
__device__ __align__(16) __half g_x_h[(size_t)MROWS * DMODEL];
__device__ __align__(16) __half g_wq_h[(size_t)3 * DMODEL * DMODEL];
__device__ __align__(16) __half g_wp_h[(size_t)DMODEL * DMODEL];
__device__ __align__(16) __half g_att_h[(size_t)MROWS * DMODEL];

// ---------------------------------------------------------------------------
// PTX helpers
// ---------------------------------------------------------------------------
__device__ __forceinline__ void cp16(uint32_t dst, const void* src) {
    asm volatile("cp.async.cg.shared.global [%0], [%1], 16;" :: "r"(dst), "l"(src));
}
__device__ __forceinline__ void cp_commit() {
    asm volatile("cp.async.commit_group;" ::: "memory");
}
template <int N>
__device__ __forceinline__ void cp_wait() {
    asm volatile("cp.async.wait_group %0;" :: "n"(N) : "memory");
}
__device__ __forceinline__ void ldsm4(uint32_t* r, uint32_t addr) {
    asm volatile("ldmatrix.sync.aligned.m8n8.x4.shared.b16 {%0,%1,%2,%3}, [%4];"
                 : "=r"(r[0]), "=r"(r[1]), "=r"(r[2]), "=r"(r[3]) : "r"(addr));
}
__device__ __forceinline__ void mma16816(float* d, const uint32_t* a,
                                         uint32_t b0, uint32_t b1) {
    asm volatile(
        "mma.sync.aligned.m16n8k16.row.col.f32.f16.f16.f32 "
        "{%0,%1,%2,%3},{%4,%5,%6,%7},{%8,%9},{%0,%1,%2,%3};"
        : "+f"(d[0]), "+f"(d[1]), "+f"(d[2]), "+f"(d[3])
        : "r"(a[0]), "r"(a[1]), "r"(a[2]), "r"(a[3]), "r"(b0), "r"(b1));
}

// SW128 swizzle over 128B rows: 16B chunk c (0..7) XOR row&7.
#define SWZ8(row, c) (((c) ^ ((row) & 7)))

// ---------------------------------------------------------------------------
// Merged cast: fp32 -> fp16 for x, w_qkv, w_proj in ONE launch.
// ---------------------------------------------------------------------------
__global__ void cast_all(const float4* __restrict__ x,   __half2* __restrict__ xo,
                         const float4* __restrict__ wq,  __half2* __restrict__ wqo,
                         const float4* __restrict__ wp,  __half2* __restrict__ wpo)
{
    const int n4x = MROWS * DMODEL / 4;            // 2M
    const int n4q = 3 * DMODEL * DMODEL / 4;       // 786432
    const int n4p = DMODEL * DMODEL / 4;           // 262144
    const int stride = gridDim.x * blockDim.x;
    int i = blockIdx.x * blockDim.x + threadIdx.x;
    for (; i < n4x + n4q + n4p; i += stride) {
        const float4* src; __half2* dst; int k;
        if (i < n4x)              { src = x;  dst = xo;  k = i; }
        else if (i < n4x + n4q)   { src = wq; dst = wqo; k = i - n4x; }
        else                      { src = wp; dst = wpo; k = i - n4x - n4q; }
        float4 v = src[k];
        __half2 h0; h0.x = __float2half(v.x); h0.y = __float2half(v.y);
        __half2 h1; h1.x = __float2half(v.z); h1.y = __float2half(v.w);
        dst[2 * k] = h0;  dst[2 * k + 1] = h1;
    }
}

// ---------------------------------------------------------------------------
// Tensor-core GEMM (TN): fp16 in, fp32 acc. 128x128x64 CTA tile.
// R17: 512 threads, 16 warps in a 4x4 grid, warp tile 32x32 (32 accumulators
// per thread) -> regs <= 64 -> 2 CTAs/SM = 32 warps/SM (8 per SMSP), doubling
// latency coverage over the 8-warp version. 3-stage cp.async pipeline.
// ---------------------------------------------------------------------------
#define STAGE_BYTES 32768
#define NSTAGE 3
#define GEMM_SMEM (NSTAGE * STAGE_BYTES)

template <bool HALF_OUT>
__global__ __launch_bounds__(512, 2)
void gemm_fp16(const __half* __restrict__ A,
               const __half* __restrict__ B,
               const float* __restrict__ bias,
               void* __restrict__ Cv,
               int M, int N, int K)
{
    extern __shared__ char smem[];
    const uint32_t sbase = (uint32_t)__cvta_generic_to_shared(smem);

    const int tid  = threadIdx.x;
    const int lane = tid & 31;
    const int warp = tid >> 5;                 // 0..15
    const int bm = blockIdx.y * 128;
    const int bn = blockIdx.x * 128;
    const int wm = (warp >> 2) * 32;           // 4 row groups
    const int wn = (warp & 3) * 32;            // 4 col groups

    // ---- cp.async: thread -> row tid>>2, chunks {c0, c0+1} in A and B ----
    const int lrow = tid >> 2;                 // 0..127
    const int c0   = (tid & 3) * 2;
    const __half* srcA = A + (size_t)(bm + lrow) * K;
    const __half* srcB = B + (size_t)(bn + lrow) * K;
    const uint32_t sd0 = lrow * 128 + SWZ8(lrow, c0) * 16;
    const uint32_t sd1 = lrow * 128 + SWZ8(lrow, c0 + 1) * 16;

    auto load_stage = [&](int s, int k0) {
        const uint32_t base = sbase + s * STAGE_BYTES;
        cp16(base + sd0, srcA + k0 + c0 * 8);
        cp16(base + sd1, srcA + k0 + (c0 + 1) * 8);
        cp16(base + 16384 + sd0, srcB + k0 + c0 * 8);
        cp16(base + 16384 + sd1, srcB + k0 + (c0 + 1) * 8);
        cp_commit();
    };

    float acc[2][4][4];
#pragma unroll
    for (int i = 0; i < 2; i++)
#pragma unroll
        for (int j = 0; j < 4; j++)
#pragma unroll
            for (int k = 0; k < 4; k++) acc[i][j][k] = 0.f;

    const int NIT = K >> 6;                    // 16
    load_stage(0, 0);
    load_stage(1, 64);

    const int r16 = lane & 15;
    const int khalf = lane >> 4;
    const int wrot = warp & 3;

#pragma unroll 1
    for (int it = 0; it < NIT; it++) {
        if (it + 1 < NIT) cp_wait<1>(); else cp_wait<0>();
        __syncthreads();

        if (it + 2 < NIT) {
            int s2 = it + 2;
            s2 -= (s2 / 3) * 3;
            load_stage(s2, (it + 2) * 64);
        }

        const int s = it - (it / 3) * 3;
        const uint32_t stbase = sbase + s * STAGE_BYTES;

        // Four K16 steps; warps start at staggered steps.
#pragma unroll
        for (int kx = 0; kx < 4; kx++) {
            const int kk = (kx + wrot) & 3;
            const int kc = kk * 2 + khalf;     // 16B chunk index 0..7

            uint32_t bfr[2][4];
#pragma unroll
            for (int ng = 0; ng < 2; ng++) {
                const int row = wn + ng * 16 + r16;
                const uint32_t off = row * 128 + SWZ8(row, kc) * 16;
                ldsm4(bfr[ng], stbase + 16384 + off);
            }
#pragma unroll
            for (int mb = 0; mb < 2; mb++) {
                uint32_t afr[4];
                const int row = wm + mb * 16 + r16;
                const uint32_t off = row * 128 + SWZ8(row, kc) * 16;
                ldsm4(afr, stbase + off);
#pragma unroll
                for (int nb = 0; nb < 4; nb++) {
                    const int ng = nb >> 1, j = nb & 1;
                    mma16816(acc[mb][nb], afr, bfr[ng][j], bfr[ng][2 + j]);
                }
            }
        }
    }

    // ---- Epilogue: bias add; fp16 or fp32 stores ----
    const int g  = lane >> 2;
    const int t2 = (lane & 3) * 2;
#pragma unroll
    for (int nb = 0; nb < 4; nb++) {
        const int col = bn + wn + nb * 8 + t2;
        const float bx = __ldg(bias + col), by = __ldg(bias + col + 1);
#pragma unroll
        for (int mb = 0; mb < 2; mb++) {
            const int row = bm + wm + mb * 16 + g;
            if (HALF_OUT) {
                __half* C = (__half*)Cv;
                __half2 v0, v1;
                v0.x = __float2half(acc[mb][nb][0] + bx);
                v0.y = __float2half(acc[mb][nb][1] + by);
                v1.x = __float2half(acc[mb][nb][2] + bx);
                v1.y = __float2half(acc[mb][nb][3] + by);
                *(__half2*)(C + (size_t)row * N + col)       = v0;
                *(__half2*)(C + (size_t)(row + 8) * N + col) = v1;
            } else {
                float* C = (float*)Cv;
                float2 v0 = make_float2(acc[mb][nb][0] + bx, acc[mb][nb][1] + by);
                float2 v1 = make_float2(acc[mb][nb][2] + bx, acc[mb][nb][3] + by);
                *(float2*)(C + (size_t)row * N + col)       = v0;
                *(float2*)(C + (size_t)(row + 8) * N + col) = v1;
            }
        }
    }
}

// ---------------------------------------------------------------------------
// Banded attention (smem-tiled, proven round 16). Block = (b, 16 t) x 16 h.
// ---------------------------------------------------------------------------
#define ATT_ROWS   24
#define ATT_ROW_B  2048
#define ATT_TILE_B (ATT_ROWS * ATT_ROW_B)      // 48KB
#define ATT_SMEM   (2 * ATT_TILE_B)            // 96KB

__device__ __forceinline__ float dot8s(uint4 a, uint4 b) {
    const __half2* ah = (const __half2*)&a;
    const __half2* bh = (const __half2*)&b;
    float r = 0.f;
#pragma unroll
    for (int i = 0; i < 4; i++) {
        float2 af = __half22float2(ah[i]);
        float2 bf = __half22float2(bh[i]);
        r = fmaf(af.x, bf.x, r);
        r = fmaf(af.y, bf.y, r);
    }
    return r;
}

__global__ __launch_bounds__(256, 2)
void focal_attn_s(const __half* __restrict__ qkv,
                  __half* __restrict__ out_h)
{
    extern __shared__ char smem[];
    __half* ks = (__half*)smem;
    __half* vs = (__half*)(smem + ATT_TILE_B);

    const int tid = threadIdx.x;
    const int b   = blockIdx.x >> 7;
    const int t0  = (blockIdx.x & 127) * 16;

    const size_t row_stride = 3 * DMODEL;
    const __half* kg = qkv + (size_t)(b * TLEN) * row_stride + DMODEL;
    const __half* vg = kg + DMODEL;

#pragma unroll
    for (int i = 0; i < 12; i++) {
        const int idx  = tid + i * 256;
        const int lrow = idx >> 7;
        const int ch   = idx & 127;
        const int hh   = ch >> 3;
        const int cc   = ch & 7;
        const int j    = t0 - RAD + lrow;
        const uint32_t dst = lrow * ATT_ROW_B + hh * 128 + ((cc ^ (hh & 7)) * 16);
        uint4 kvv = make_uint4(0, 0, 0, 0), vvv = make_uint4(0, 0, 0, 0);
        if ((unsigned)j < (unsigned)TLEN) {
            kvv = *(const uint4*)(kg + (size_t)j * row_stride + ch * 8);
            vvv = *(const uint4*)(vg + (size_t)j * row_stride + ch * 8);
        }
        *(uint4*)((char*)ks + dst) = kvv;
        *(uint4*)((char*)vs + dst) = vvv;
    }
    __syncthreads();

    const int tl = tid >> 4;
    const int h  = tid & 15;
    const int t  = t0 + tl;
    const int bt = b * TLEN + t;

    uint4 qv[8];
    const __half* qrow = qkv + (size_t)bt * row_stride + h * HDIM;
#pragma unroll
    for (int c = 0; c < 8; c++) qv[c] = *(const uint4*)(qrow + c * 8);

    bool ok[9];
#pragma unroll
    for (int jj = 0; jj < 9; jj++)
        ok[jj] = ((unsigned)(t - RAD + jj) < (unsigned)TLEN);

    float s[9];
#pragma unroll
    for (int jj = 0; jj < 9; jj++) {
        const char* kr = (char*)ks + (tl + jj) * ATT_ROW_B + h * 128;
        float acc = 0.f;
#pragma unroll
        for (int c = 0; c < 8; c++)
            acc += dot8s(qv[c], *(const uint4*)(kr + ((c ^ (h & 7)) * 16)));
        s[jj] = acc * 0.125f;
    }

    float m = -INFINITY;
#pragma unroll
    for (int jj = 0; jj < 9; jj++)
        if (ok[jj]) m = fmaxf(m, s[jj]);

    float p[9], psum = 0.f;
#pragma unroll
    for (int jj = 0; jj < 9; jj++) {
        p[jj] = ok[jj] ? expf(s[jj] - m) : 0.f;
        psum += p[jj];
    }
    const float inv = 1.f / psum;
#pragma unroll
    for (int jj = 0; jj < 9; jj++) p[jj] *= inv;

    float ax[32], ay[32];
#pragma unroll
    for (int i = 0; i < 32; i++) { ax[i] = 0.f; ay[i] = 0.f; }
#pragma unroll
    for (int jj = 0; jj < 9; jj++) {
        const char* vr = (char*)vs + (tl + jj) * ATT_ROW_B + h * 128;
        const float pw = p[jj];
#pragma unroll
        for (int c = 0; c < 8; c++) {
            const uint4 vv = *(const uint4*)(vr + ((c ^ (h & 7)) * 16));
            const __half2* vh = (const __half2*)&vv;
#pragma unroll
            for (int i = 0; i < 4; i++) {
                float2 vf = __half22float2(vh[i]);
                ax[c * 4 + i] = fmaf(pw, vf.x, ax[c * 4 + i]);
                ay[c * 4 + i] = fmaf(pw, vf.y, ay[c * 4 + i]);
            }
        }
    }

    __half* orow = out_h + (size_t)bt * DMODEL + h * HDIM;
#pragma unroll
    for (int c = 0; c < 8; c++) {
        uint4 ov;
        __half2* oh = (__half2*)&ov;
#pragma unroll
        for (int i = 0; i < 4; i++) {
            __half2 hv;
            hv.x = __float2half(ax[c * 4 + i]);
            hv.y = __float2half(ay[c * 4 + i]);
            oh[i] = hv;
        }
        *(uint4*)(orow + c * 8) = ov;
    }
}

// ---------------------------------------------------------------------------
// Launch: merged cast -> QKV GEMM (fp16 out) -> attention -> proj GEMM
// ---------------------------------------------------------------------------
extern "C" void kernel_launch(void* const* d_in, const int* in_sizes, int n_in,
                              void* d_out, int out_size)
{
    const float* x      = (const float*)d_in[0];
    const float* w_qkv  = (const float*)d_in[1];
    const float* b_qkv  = (const float*)d_in[2];
    const float* w_proj = (const float*)d_in[3];
    const float* b_proj = (const float*)d_in[4];
    float* out = (float*)d_out;

    __half *qkvh, *xh, *wqh, *wph, *ath;
    cudaGetSymbolAddress((void**)&qkvh, g_qkv_h);
    cudaGetSymbolAddress((void**)&xh,  g_x_h);
    cudaGetSymbolAddress((void**)&wqh, g_wq_h);
    cudaGetSymbolAddress((void**)&wph, g_wp_h);
    cudaGetSymbolAddress((void**)&ath, g_att_h);

    cudaFuncSetAttribute(gemm_fp16<true>,
                         cudaFuncAttributeMaxDynamicSharedMemorySize, GEMM_SMEM);
    cudaFuncSetAttribute(gemm_fp16<false>,
                         cudaFuncAttributeMaxDynamicSharedMemorySize, GEMM_SMEM);
    cudaFuncSetAttribute(focal_attn_s,
                         cudaFuncAttributeMaxDynamicSharedMemorySize, ATT_SMEM);

    // Merged cast (one launch)
    cast_all<<<2048, 256>>>((const float4*)x,      (__half2*)xh,
                            (const float4*)w_qkv,  (__half2*)wqh,
                            (const float4*)w_proj, (__half2*)wph);

    // GEMM1: qkv[8192,3072] = x @ w_qkv^T + b_qkv  (fp16 out)
    {
        dim3 grid(3 * DMODEL / 128, MROWS / 128);   // 24 x 64
        gemm_fp16<true><<<grid, 512, GEMM_SMEM>>>(xh, wqh, b_qkv, qkvh,
                                                  MROWS, 3 * DMODEL, DMODEL);
    }

    // Attention: 512 blocks, smem-tiled
    focal_attn_s<<<BSZ * (TLEN / 16), 256, ATT_SMEM>>>(qkvh, ath);

    // GEMM2: out[8192,1024] = att @ w_proj^T + b_proj  (fp32 out)
    {
        dim3 grid(DMODEL / 128, MROWS / 128);       // 8 x 64
        gemm_fp16<false><<<grid, 512, GEMM_SMEM>>>(ath, wph, b_proj, out,
                                                   MROWS, DMODEL, DMODEL);
    }
}